// round 3
// baseline (speedup 1.0000x reference)
#include <cuda_runtime.h>
typedef unsigned long long u64;

#define TT 2048
#define BB 4096
#define OUTLEN 25
#define TPW 20
#define WPD 205
#define NWIN (TT/8)

__device__ float g_y[BB * 18];

__device__ __forceinline__ u64 pack2(float lo, float hi) {
    u64 d; asm("mov.b64 %0,{%1,%2};" : "=l"(d) : "f"(lo), "f"(hi)); return d;
}
__device__ __forceinline__ void unpack2(u64 v, float& lo, float& hi) {
    asm("mov.b64 {%0,%1},%2;" : "=f"(lo), "=f"(hi) : "l"(v));
}
__device__ __forceinline__ u64 fma2(u64 a, u64 b, u64 c) {
    u64 d; asm("fma.rn.f32x2 %0,%1,%2,%3;" : "=l"(d) : "l"(a), "l"(b), "l"(c)); return d;
}
__device__ __forceinline__ u64 mul2(u64 a, u64 b) {
    u64 d; asm("mul.rn.f32x2 %0,%1,%2;" : "=l"(d) : "l"(a), "l"(b)); return d;
}
__device__ __forceinline__ u64 add2(u64 a, u64 b) {
    u64 d; asm("add.rn.f32x2 %0,%1,%2;" : "=l"(d) : "l"(a), "l"(b)); return d;
}
__device__ __forceinline__ float tanha(float x) {
    float y; asm("tanh.approx.f32 %0,%1;" : "=f"(y) : "f"(x)); return y;
}
__device__ __forceinline__ float ftanh(float x) {
    x = fminf(fmaxf(x, -9.0f), 9.0f);
    float e = __expf(2.0f * x);
    return __fdividef(e - 1.0f, e + 1.0f);
}

// ---------------------------------------------------------------------------
// Stage 1: bidirectional Elman RNN H1=9 over T=2048, f32x2-packed.
// Warp = 20 tasks (10 lane-triples x 2 batches packed lo/hi). Lane r of a
// triple owns units 3r..3r+2 for both batches. 8-step windows of x staged
// through warp-local smem (coalesced LDG, double buffered).
// Last 4 windows use precise tanh; earlier windows use tanh.approx (errors
// contract away; see round notes).
// ---------------------------------------------------------------------------
__global__ __launch_bounds__(128) void rnn1_kernel(
    const float* __restrict__ x,
    const float* __restrict__ wih_f, const float* __restrict__ whh_f,
    const float* __restrict__ bih_f, const float* __restrict__ bhh_f,
    const float* __restrict__ wih_b, const float* __restrict__ whh_b,
    const float* __restrict__ bih_b, const float* __restrict__ bhh_b)
{
    __shared__ float4 sbuf[4][2][220];   // [warp][buf][task*11 + chunk]

    const int wIn  = threadIdx.x >> 5;
    const int lane = threadIdx.x & 31;
    const int wid  = blockIdx.x * 4 + wIn;
    if (wid >= 2 * WPD) return;

    const bool bwd = (wid >= WPD);
    const int  wg  = bwd ? wid - WPD : wid;
    const int  tri = min(lane / 3, 9);   // lanes 30,31 shadow triple 9
    const int  r   = lane % 3;
    const int  srcbase = tri * 3;

    const float* wih = bwd ? wih_b : wih_f;
    const float* whh = bwd ? whh_b : whh_f;
    const float* bih = bwd ? bih_b : bih_f;
    const float* bhh = bwd ? bhh_b : bhh_f;

    u64 WX[3][5], WH[3][9], B2[3];
    #pragma unroll
    for (int m = 0; m < 3; m++) {
        const int j = 3 * r + m;
        #pragma unroll
        for (int k = 0; k < 5; k++) { float w = wih[j * 5 + k]; WX[m][k] = pack2(w, w); }
        #pragma unroll
        for (int i = 0; i < 9; i++) { float w = whh[j * 9 + i]; WH[m][i] = pack2(w, w); }
        float bv = bih[j] + bhh[j];
        B2[m] = pack2(bv, bv);
    }

    // loader: linear float4 idx = lane + 32*j over 200 (= 20 tasks x 10 chunks)
    const char* xc = (const char*)x;
    size_t   gbase[7];
    unsigned sidx[7];
    #pragma unroll
    for (int j = 0; j < 7; j++) {
        int idx = lane + 32 * j;
        int tau = idx / 10, c = idx - tau * 10;
        int bt  = wg * TPW + tau;
        int bc  = min(bt, BB - 1);
        gbase[j] = (size_t)bc * (TT * 20) + (size_t)c * 16;
        sidx[j]  = (unsigned)(tau * 11 + c);
    }
    float4 pf[7];

    #define PFLOAD(g) do {                                                    \
        size_t wb = (size_t)(bwd ? (TT - 8 - 8 * (g)) : (8 * (g))) * 20;      \
        _Pragma("unroll")                                                     \
        for (int j = 0; j < 7; j++)                                           \
            if (lane + 32 * j < 200)                                          \
                pf[j] = *reinterpret_cast<const float4*>(xc + gbase[j] + wb); \
    } while (0)

    #define STSW(buf) do {                                                    \
        _Pragma("unroll")                                                     \
        for (int j = 0; j < 7; j++)                                           \
            if (lane + 32 * j < 200) sbuf[wIn][buf][sidx[j]] = pf[j];         \
    } while (0)

    u64 H2[9];
    #pragma unroll
    for (int i = 0; i < 9; i++) H2[i] = 0ull;
    float hA_[3] = {0.f, 0.f, 0.f}, hB_[3] = {0.f, 0.f, 0.f};

    #define STEP(TANHF, X0, X1, X2, X3, X4) do {                              \
        _Pragma("unroll")                                                     \
        for (int m = 0; m < 3; m++) {                                         \
            u64 p = B2[m];                                                    \
            p = fma2(WX[m][0], (X0), p); p = fma2(WX[m][1], (X1), p);         \
            p = fma2(WX[m][2], (X2), p); p = fma2(WX[m][3], (X3), p);         \
            p = fma2(WX[m][4], (X4), p);                                      \
            p = fma2(WH[m][7], H2[7], p); p = fma2(WH[m][8], H2[8], p);       \
            u64 q = mul2(WH[m][0], H2[0]);                                    \
            q = fma2(WH[m][1], H2[1], q); q = fma2(WH[m][2], H2[2], q);       \
            q = fma2(WH[m][3], H2[3], q); q = fma2(WH[m][4], H2[4], q);       \
            q = fma2(WH[m][5], H2[5], q); q = fma2(WH[m][6], H2[6], q);       \
            float sa, sb; unpack2(add2(p, q), sa, sb);                        \
            hA_[m] = TANHF(sa); hB_[m] = TANHF(sb);                           \
        }                                                                     \
        u64 hp0 = pack2(hA_[0], hB_[0]);                                      \
        u64 hp1 = pack2(hA_[1], hB_[1]);                                      \
        u64 hp2 = pack2(hA_[2], hB_[2]);                                      \
        _Pragma("unroll")                                                     \
        for (int s = 0; s < 3; s++) {                                         \
            H2[3*s+0] = __shfl_sync(0xffffffffu, hp0, srcbase + s);           \
            H2[3*s+1] = __shfl_sync(0xffffffffu, hp1, srcbase + s);           \
            H2[3*s+2] = __shfl_sync(0xffffffffu, hp2, srcbase + s);           \
        }                                                                     \
    } while (0)

    #define CONS(TANHF, buf, sub, REV) do {                                   \
        const float4* pA = &sbuf[wIn][buf][tri * 22 + (sub) * 5];             \
        const float4* pB = pA + 11;                                           \
        float fa[20], fb[20];                                                 \
        _Pragma("unroll")                                                     \
        for (int c = 0; c < 5; c++) {                                         \
            float4 va = pA[c], vb = pB[c];                                    \
            fa[4*c] = va.x; fa[4*c+1] = va.y; fa[4*c+2] = va.z; fa[4*c+3] = va.w; \
            fb[4*c] = vb.x; fb[4*c+1] = vb.y; fb[4*c+2] = vb.z; fb[4*c+3] = vb.w; \
        }                                                                     \
        _Pragma("unroll")                                                     \
        for (int q0 = 0; q0 < 4; q0++) {                                      \
            const int qq = (REV) ? 3 - q0 : q0;                               \
            STEP(TANHF, pack2(fa[qq*5+0], fb[qq*5+0]),                        \
                        pack2(fa[qq*5+1], fb[qq*5+1]),                        \
                        pack2(fa[qq*5+2], fb[qq*5+2]),                        \
                        pack2(fa[qq*5+3], fb[qq*5+3]),                        \
                        pack2(fa[qq*5+4], fb[qq*5+4]));                       \
        }                                                                     \
    } while (0)

    PFLOAD(0);
    STSW(0);
    PFLOAD(1);
    __syncwarp();
    for (int g = 0; g < NWIN; g++) {
        const int buf = g & 1;
        if (g < NWIN - 4) {
            if (!bwd) { CONS(tanha, buf, 0, 0); CONS(tanha, buf, 1, 0); }
            else      { CONS(tanha, buf, 1, 1); CONS(tanha, buf, 0, 1); }
        } else {
            if (!bwd) { CONS(ftanh, buf, 0, 0); CONS(ftanh, buf, 1, 0); }
            else      { CONS(ftanh, buf, 1, 1); CONS(ftanh, buf, 0, 1); }
        }
        if (g + 1 < NWIN) {
            STSW((g + 1) & 1);
            if (g + 2 < NWIN) PFLOAD(g + 2);
            __syncwarp();
        }
    }

    if (lane < 30) {
        const int dirOff = bwd ? 9 : 0;
        const int bA = wg * TPW + 2 * tri;
        const int bB = bA + 1;
        if (bA < BB) {
            #pragma unroll
            for (int m = 0; m < 3; m++) g_y[bA * 18 + dirOff + 3*r + m] = hA_[m];
        }
        if (bB < BB) {
            #pragma unroll
            for (int m = 0; m < 3; m++) g_y[bB * 18 + dirOff + 3*r + m] = hB_[m];
        }
    }
    #undef PFLOAD
    #undef STSW
    #undef STEP
    #undef CONS
}

// ---------------------------------------------------------------------------
// Stage 2: H2=32 RNN, 25 steps + linear 32->3. Warp per batch, lane = unit.
// Recurrence via smem broadcast (1 STS + 8 LDS.128/step, no shfl); hs[][]
// doubles as the transposed ys for the output epilogue.
// ---------------------------------------------------------------------------
__global__ __launch_bounds__(256) void rnn2_kernel(
    const float* __restrict__ wih2, const float* __restrict__ whh2,
    const float* __restrict__ bih2, const float* __restrict__ bhh2,
    const float* __restrict__ wout, const float* __restrict__ bout,
    float* __restrict__ out)
{
    __shared__ float hs[8][OUTLEN][36];   // stride 36 keeps rows 16B-aligned
    __shared__ float swo[96];

    const int wIn = threadIdx.x >> 5;
    const int j   = threadIdx.x & 31;
    const int b   = blockIdx.x * 8 + wIn;

    if (threadIdx.x < 96) swo[threadIdx.x] = wout[threadIdx.x];
    __syncthreads();

    float Wh[32], Wi[18];
    #pragma unroll
    for (int i = 0; i < 32; i++) Wh[i] = whh2[j * 32 + i];
    #pragma unroll
    for (int k = 0; k < 18; k++) Wi[k] = wih2[j * 18 + k];
    const float bj = bih2[j] + bhh2[j];

    // t = 0
    const float* y = g_y + (size_t)b * 18;
    float z = bj;
    #pragma unroll
    for (int k = 0; k < 18; k++) z = fmaf(Wi[k], y[k], z);
    float h = ftanh(z);
    hs[wIn][0][j] = h;

    for (int t = 1; t < OUTLEN; t++) {
        __syncwarp();
        const float4* hp = reinterpret_cast<const float4*>(&hs[wIn][t - 1][0]);
        float acc = bj;
        #pragma unroll
        for (int c = 0; c < 8; c++) {
            float4 v = hp[c];
            acc = fmaf(Wh[4*c+0], v.x, acc);
            acc = fmaf(Wh[4*c+1], v.y, acc);
            acc = fmaf(Wh[4*c+2], v.z, acc);
            acc = fmaf(Wh[4*c+3], v.w, acc);
        }
        h = ftanh(acc);
        hs[wIn][t][j] = h;
    }
    __syncwarp();

    float* op = out + (size_t)b * (OUTLEN * 3);
    for (int p = j; p < OUTLEN * 3; p += 32) {
        const int t = p / 3, o = p - 3 * t;
        const float4* yr = reinterpret_cast<const float4*>(&hs[wIn][t][0]);
        const float4* wr = reinterpret_cast<const float4*>(&swo[o * 32]);
        float acc = bout[o];
        #pragma unroll
        for (int c = 0; c < 8; c++) {
            float4 yv = yr[c], wv = wr[c];
            acc = fmaf(yv.x, wv.x, acc);
            acc = fmaf(yv.y, wv.y, acc);
            acc = fmaf(yv.z, wv.z, acc);
            acc = fmaf(yv.w, wv.w, acc);
        }
        op[p] = acc;
    }
}

// ---------------------------------------------------------------------------
extern "C" void kernel_launch(void* const* d_in, const int* in_sizes, int n_in,
                              void* d_out, int out_size)
{
    const float* x     = (const float*)d_in[0];
    const float* wih_f = (const float*)d_in[1];
    const float* whh_f = (const float*)d_in[2];
    const float* bih_f = (const float*)d_in[3];
    const float* bhh_f = (const float*)d_in[4];
    const float* wih_b = (const float*)d_in[5];
    const float* whh_b = (const float*)d_in[6];
    const float* bih_b = (const float*)d_in[7];
    const float* bhh_b = (const float*)d_in[8];
    const float* wih2  = (const float*)d_in[9];
    const float* whh2  = (const float*)d_in[10];
    const float* bih2  = (const float*)d_in[11];
    const float* bhh2  = (const float*)d_in[12];
    const float* wout  = (const float*)d_in[13];
    const float* bout  = (const float*)d_in[14];
    float* out = (float*)d_out;

    rnn1_kernel<<<103, 128>>>(x, wih_f, whh_f, bih_f, bhh_f,
                              wih_b, whh_b, bih_b, bhh_b);
    rnn2_kernel<<<512, 256>>>(wih2, whh2, bih2, bhh2, wout, bout, out);
}

// round 4
// speedup vs baseline: 1.0162x; 1.0162x over previous
#include <cuda_runtime.h>
typedef unsigned long long u64;

#define TT 2048
#define BB 4096
#define OUTLEN 25
#define WPD 205          // warps per direction (ceil(4096/20))
#define NWIN (TT/8)      // 256 windows of 8 steps

__device__ float g_y[BB * 18];

__device__ __forceinline__ u64 pack2(float lo, float hi) {
    u64 d; asm("mov.b64 %0,{%1,%2};" : "=l"(d) : "f"(lo), "f"(hi)); return d;
}
__device__ __forceinline__ void unpack2(u64 v, float& lo, float& hi) {
    asm("mov.b64 {%0,%1},%2;" : "=f"(lo), "=f"(hi) : "l"(v));
}
__device__ __forceinline__ u64 fma2(u64 a, u64 b, u64 c) {
    u64 d; asm("fma.rn.f32x2 %0,%1,%2,%3;" : "=l"(d) : "l"(a), "l"(b), "l"(c)); return d;
}
__device__ __forceinline__ u64 mul2(u64 a, u64 b) {
    u64 d; asm("mul.rn.f32x2 %0,%1,%2;" : "=l"(d) : "l"(a), "l"(b)); return d;
}
__device__ __forceinline__ u64 add2(u64 a, u64 b) {
    u64 d; asm("add.rn.f32x2 %0,%1,%2;" : "=l"(d) : "l"(a), "l"(b)); return d;
}
__device__ __forceinline__ float tanha(float x) {
    float y; asm("tanh.approx.f32 %0,%1;" : "=f"(y) : "f"(x)); return y;
}
__device__ __forceinline__ float ftanh(float x) {
    x = fminf(fmaxf(x, -9.0f), 9.0f);
    float e = __expf(2.0f * x);
    return __fdividef(e - 1.0f, e + 1.0f);
}

// ---------------------------------------------------------------------------
// Stage 1: bidirectional Elman RNN H1=9, T=2048, f32x2-packed (2 batches per
// lane-triple; 20 batches/warp). 103 CTAs x 4 warps -> <=1 warp per SMSP
// (latency-bound regime). x staged per-warp in smem PRE-PACKED as (A,B)
// float2 pairs: consumer does 5 x LDS.64 per step, no repacking.
// tanh.approx for steps 0..2015, precise tanh for the last 32 steps
// (contraction rho~0.33 measured in R0 kills the approx error).
// ---------------------------------------------------------------------------
__global__ __launch_bounds__(128, 1) void rnn1_kernel(
    const float* __restrict__ x,
    const float* __restrict__ wih_f, const float* __restrict__ whh_f,
    const float* __restrict__ bih_f, const float* __restrict__ bhh_f,
    const float* __restrict__ wih_b, const float* __restrict__ whh_b,
    const float* __restrict__ bih_b, const float* __restrict__ bhh_b)
{
    // [warp][buf][ (q*5+k)*10 + pair ]  : packed (batchA,batchB) x-values
    __shared__ u64 sx[4][2][400];

    const int wIn  = threadIdx.x >> 5;
    const int lane = threadIdx.x & 31;
    const int wid  = blockIdx.x * 4 + wIn;
    if (wid >= 2 * WPD) return;

    const bool bwd = (wid >= WPD);
    const int  wg  = bwd ? wid - WPD : wid;
    const int  tri = min(lane / 3, 9);     // lanes 30,31 shadow pair 9
    const int  r   = lane % 3;
    const int  srcbase = 3 * tri;

    const float* wih = bwd ? wih_b : wih_f;
    const float* whh = bwd ? whh_b : whh_f;
    const float* bih = bwd ? bih_b : bih_f;
    const float* bhh = bwd ? bhh_b : bhh_f;

    // packed weights (same value both halves; both batches share direction)
    u64 WX[3][5], WH[3][9], B2[3];
    #pragma unroll
    for (int m = 0; m < 3; m++) {
        const int j = 3 * r + m;
        #pragma unroll
        for (int k = 0; k < 5; k++) { float w = wih[j * 5 + k]; WX[m][k] = pack2(w, w); }
        #pragma unroll
        for (int i = 0; i < 9; i++) { float w = whh[j * 9 + i]; WH[m][i] = pack2(w, w); }
        float bv = bih[j] + bhh[j];
        B2[m] = pack2(bv, bv);
    }

    // ---- loader: 100 pair-chunks (pair p 0..9, chunk c 0..9), lane gets
    // pc = lane, lane+32, lane+64, lane+96. Each pc: one float4 from batch
    // 2p and one from 2p+1, stored as 4 packed u64s.
    const char* xc = (const char*)x;
    size_t gA[4], gB[4];
    int    soff[4];
    #pragma unroll
    for (int k = 0; k < 4; k++) {
        int pc = lane + 32 * k;
        int pcc = min(pc, 99);
        int p = pcc / 10, c = pcc - 10 * p;
        int ba = wg * 20 + 2 * p;
        int bac = min(ba, BB - 1);
        int bbc = min(ba + 1, BB - 1);
        gA[k] = (size_t)bac * (TT * 20) + (size_t)c * 16;   // bytes
        gB[k] = (size_t)bbc * (TT * 20) + (size_t)c * 16;
        soff[k] = c * 40 + p;    // u64 index for u=0: (c*4+u)*10 + p
    }
    float4 pA[4], pB[4];

    #define PFLOAD(g) do {                                                    \
        size_t wb = (size_t)(bwd ? (TT - 8 - 8 * (g)) : (8 * (g))) * 20;      \
        _Pragma("unroll")                                                     \
        for (int k = 0; k < 4; k++)                                           \
            if (lane + 32 * k < 100) {                                        \
                pA[k] = *reinterpret_cast<const float4*>(xc + gA[k] + wb);    \
                pB[k] = *reinterpret_cast<const float4*>(xc + gB[k] + wb);    \
            }                                                                 \
    } while (0)

    #define STSW(buf) do {                                                    \
        _Pragma("unroll")                                                     \
        for (int k = 0; k < 4; k++)                                           \
            if (lane + 32 * k < 100) {                                        \
                u64* s = &sx[wIn][buf][soff[k]];                              \
                s[0]  = pack2(pA[k].x, pB[k].x);                              \
                s[10] = pack2(pA[k].y, pB[k].y);                              \
                s[20] = pack2(pA[k].z, pB[k].z);                              \
                s[30] = pack2(pA[k].w, pB[k].w);                              \
            }                                                                 \
    } while (0)

    u64 H2[9];
    #pragma unroll
    for (int i = 0; i < 9; i++) H2[i] = 0ull;
    float hA_[3] = {0.f, 0.f, 0.f}, hB_[3] = {0.f, 0.f, 0.f};

    #define STEP(TANHF, buf, q) do {                                          \
        const u64* xs = &sx[wIn][buf][(q) * 50 + tri];                        \
        u64 X0 = xs[0], X1 = xs[10], X2 = xs[20], X3 = xs[30], X4 = xs[40];   \
        _Pragma("unroll")                                                     \
        for (int m = 0; m < 3; m++) {                                         \
            u64 pv = B2[m];                                                   \
            pv = fma2(WX[m][0], X0, pv); pv = fma2(WX[m][1], X1, pv);         \
            pv = fma2(WX[m][2], X2, pv); pv = fma2(WX[m][3], X3, pv);         \
            pv = fma2(WX[m][4], X4, pv);                                      \
            u64 q1 = mul2(WH[m][0], H2[0]);                                   \
            q1 = fma2(WH[m][1], H2[1], q1); q1 = fma2(WH[m][2], H2[2], q1);   \
            u64 q2 = mul2(WH[m][3], H2[3]);                                   \
            q2 = fma2(WH[m][4], H2[4], q2); q2 = fma2(WH[m][5], H2[5], q2);   \
            u64 q3 = mul2(WH[m][6], H2[6]);                                   \
            q3 = fma2(WH[m][7], H2[7], q3); q3 = fma2(WH[m][8], H2[8], q3);   \
            u64 a = add2(add2(pv, q1), add2(q2, q3));                         \
            float sa, sb; unpack2(a, sa, sb);                                 \
            hA_[m] = TANHF(sa); hB_[m] = TANHF(sb);                           \
        }                                                                     \
        u64 hp0 = pack2(hA_[0], hB_[0]);                                      \
        u64 hp1 = pack2(hA_[1], hB_[1]);                                      \
        u64 hp2 = pack2(hA_[2], hB_[2]);                                      \
        _Pragma("unroll")                                                     \
        for (int s = 0; s < 3; s++) {                                         \
            H2[3*s+0] = __shfl_sync(0xffffffffu, hp0, srcbase + s);           \
            H2[3*s+1] = __shfl_sync(0xffffffffu, hp1, srcbase + s);           \
            H2[3*s+2] = __shfl_sync(0xffffffffu, hp2, srcbase + s);           \
        }                                                                     \
    } while (0)

    #define CONS(TANHF, buf) do {                                             \
        if (!bwd) {                                                           \
            STEP(TANHF, buf, 0); STEP(TANHF, buf, 1);                         \
            STEP(TANHF, buf, 2); STEP(TANHF, buf, 3);                         \
            STEP(TANHF, buf, 4); STEP(TANHF, buf, 5);                         \
            STEP(TANHF, buf, 6); STEP(TANHF, buf, 7);                         \
        } else {                                                              \
            STEP(TANHF, buf, 7); STEP(TANHF, buf, 6);                         \
            STEP(TANHF, buf, 5); STEP(TANHF, buf, 4);                         \
            STEP(TANHF, buf, 3); STEP(TANHF, buf, 2);                         \
            STEP(TANHF, buf, 1); STEP(TANHF, buf, 0);                         \
        }                                                                     \
    } while (0)

    PFLOAD(0);
    STSW(0);
    PFLOAD(1);
    __syncwarp();
    for (int g = 0; g < NWIN; g++) {
        const int buf = g & 1;
        if (g < NWIN - 4) CONS(tanha, buf);
        else              CONS(ftanh, buf);
        if (g + 1 < NWIN) {
            STSW((g + 1) & 1);
            if (g + 2 < NWIN) PFLOAD(g + 2);
            __syncwarp();
        }
    }

    if (lane < 30) {
        const int dirOff = bwd ? 9 : 0;
        const int bA = wg * 20 + 2 * tri;
        const int bB = bA + 1;
        if (bA < BB) {
            #pragma unroll
            for (int m = 0; m < 3; m++) g_y[bA * 18 + dirOff + 3*r + m] = hA_[m];
        }
        if (bB < BB) {
            #pragma unroll
            for (int m = 0; m < 3; m++) g_y[bB * 18 + dirOff + 3*r + m] = hB_[m];
        }
    }
    #undef PFLOAD
    #undef STSW
    #undef STEP
    #undef CONS
}

// ---------------------------------------------------------------------------
// Stage 2: H2=32 RNN, 25 steps + linear 32->3. Warp per batch, lane = unit.
// Weights staged in smem (coalesced) then per-lane reg rows (kills the
// strided-LDG wavefront storm ncu showed). Recurrence: smem broadcast reads
// + 4 independent accumulators. hs[][] doubles as ys for the epilogue.
// ---------------------------------------------------------------------------
__global__ __launch_bounds__(256) void rnn2_kernel(
    const float* __restrict__ wih2, const float* __restrict__ whh2,
    const float* __restrict__ bih2, const float* __restrict__ bhh2,
    const float* __restrict__ wout, const float* __restrict__ bout,
    float* __restrict__ out)
{
    __shared__ float swh[1024], swi[576], swo[96];
    __shared__ float hs[8][OUTLEN][32];

    const int tid = threadIdx.x;
    for (int i = tid; i < 1024; i += 256) swh[i] = whh2[i];
    for (int i = tid; i < 576;  i += 256) swi[i] = wih2[i];
    if (tid < 96) swo[tid] = wout[tid];
    __syncthreads();

    const int wIn = tid >> 5;
    const int j   = tid & 31;
    const int b   = blockIdx.x * 8 + wIn;

    float Wh[32];
    {
        const float4* p = reinterpret_cast<const float4*>(&swh[j * 32]);
        #pragma unroll
        for (int c = 0; c < 8; c++) {
            float4 v = p[c];
            Wh[4*c] = v.x; Wh[4*c+1] = v.y; Wh[4*c+2] = v.z; Wh[4*c+3] = v.w;
        }
    }
    float Wi[18];
    {
        const float2* p = reinterpret_cast<const float2*>(&swi[j * 18]);
        #pragma unroll
        for (int c = 0; c < 9; c++) { float2 v = p[c]; Wi[2*c] = v.x; Wi[2*c+1] = v.y; }
    }
    const float bj = bih2[j] + bhh2[j];

    // t = 0
    float z = bj;
    {
        const float2* yp = reinterpret_cast<const float2*>(g_y + (size_t)b * 18);
        #pragma unroll
        for (int c = 0; c < 9; c++) {
            float2 v = yp[c];
            z = fmaf(Wi[2*c], v.x, z);
            z = fmaf(Wi[2*c+1], v.y, z);
        }
    }
    float h = ftanh(z);
    hs[wIn][0][j] = h;

    for (int t = 1; t < OUTLEN; t++) {
        __syncwarp();
        const float4* hp = reinterpret_cast<const float4*>(&hs[wIn][t - 1][0]);
        float a0 = bj, a1 = 0.f, a2 = 0.f, a3 = 0.f;
        #pragma unroll
        for (int c = 0; c < 8; c += 4) {
            float4 v0 = hp[c],     v1 = hp[c + 1];
            float4 v2 = hp[c + 2], v3 = hp[c + 3];
            a0 = fmaf(Wh[4*c+0],  v0.x, a0); a0 = fmaf(Wh[4*c+1],  v0.y, a0);
            a1 = fmaf(Wh[4*c+2],  v0.z, a1); a1 = fmaf(Wh[4*c+3],  v0.w, a1);
            a2 = fmaf(Wh[4*c+4],  v1.x, a2); a2 = fmaf(Wh[4*c+5],  v1.y, a2);
            a3 = fmaf(Wh[4*c+6],  v1.z, a3); a3 = fmaf(Wh[4*c+7],  v1.w, a3);
            a0 = fmaf(Wh[4*c+8],  v2.x, a0); a0 = fmaf(Wh[4*c+9],  v2.y, a0);
            a1 = fmaf(Wh[4*c+10], v2.z, a1); a1 = fmaf(Wh[4*c+11], v2.w, a1);
            a2 = fmaf(Wh[4*c+12], v3.x, a2); a2 = fmaf(Wh[4*c+13], v3.y, a2);
            a3 = fmaf(Wh[4*c+14], v3.z, a3); a3 = fmaf(Wh[4*c+15], v3.w, a3);
        }
        h = ftanh((a0 + a1) + (a2 + a3));
        hs[wIn][t][j] = h;
    }
    __syncwarp();

    float* op = out + (size_t)b * (OUTLEN * 3);
    for (int p = j; p < OUTLEN * 3; p += 32) {
        const int t = p / 3, o = p - 3 * t;
        const float4* yr = reinterpret_cast<const float4*>(&hs[wIn][t][0]);
        const float4* wr = reinterpret_cast<const float4*>(&swo[o * 32]);
        float acc = bout[o];
        #pragma unroll
        for (int c = 0; c < 8; c++) {
            float4 yv = yr[c], wv = wr[c];
            acc = fmaf(yv.x, wv.x, acc);
            acc = fmaf(yv.y, wv.y, acc);
            acc = fmaf(yv.z, wv.z, acc);
            acc = fmaf(yv.w, wv.w, acc);
        }
        op[p] = acc;
    }
}

// ---------------------------------------------------------------------------
extern "C" void kernel_launch(void* const* d_in, const int* in_sizes, int n_in,
                              void* d_out, int out_size)
{
    const float* x     = (const float*)d_in[0];
    const float* wih_f = (const float*)d_in[1];
    const float* whh_f = (const float*)d_in[2];
    const float* bih_f = (const float*)d_in[3];
    const float* bhh_f = (const float*)d_in[4];
    const float* wih_b = (const float*)d_in[5];
    const float* whh_b = (const float*)d_in[6];
    const float* bih_b = (const float*)d_in[7];
    const float* bhh_b = (const float*)d_in[8];
    const float* wih2  = (const float*)d_in[9];
    const float* whh2  = (const float*)d_in[10];
    const float* bih2  = (const float*)d_in[11];
    const float* bhh2  = (const float*)d_in[12];
    const float* wout  = (const float*)d_in[13];
    const float* bout  = (const float*)d_in[14];
    float* out = (float*)d_out;

    // 103 CTAs x 4 warps = 412 warps (410 active) -> <=1 CTA per SM
    rnn1_kernel<<<103, 128>>>(x, wih_f, whh_f, bih_f, bhh_f,
                              wih_b, whh_b, bih_b, bhh_b);
    rnn2_kernel<<<512, 256>>>(wih2, whh2, bih2, bhh2, wout, bout, out);
}

// round 5
// speedup vs baseline: 1.1809x; 1.1621x over previous
#include <cuda_runtime.h>

#define TT 2048
#define BB 4096
#define OUTLEN 25
#define WPD 410            // warps per direction (10 tasks each)
#define NWIN (TT/8)        // 256 windows of 8 steps

__device__ float g_y[BB * 18];

__device__ __forceinline__ float tanha(float x) {
    float y; asm("tanh.approx.f32 %0,%1;" : "=f"(y) : "f"(x)); return y;
}
__device__ __forceinline__ float ftanh(float x) {
    x = fminf(fmaxf(x, -9.0f), 9.0f);
    float e = __expf(2.0f * x);
    return __fdividef(e - 1.0f, e + 1.0f);
}

__global__ void dummy_kernel() {}

// ---------------------------------------------------------------------------
// Stage 1: bidirectional Elman RNN H1=9, T=2048. Split-3: one (batch,dir)
// task = 3 lanes, lane r owns units 3r..3r+2; 10 tasks/warp.
// 103 CTAs x 8 warps -> uniform 2 warps/SMSP chip-wide.
// Exchange = 6 shfls/step (own units kept in regs; Whh columns permuted at
// setup so register indices stay static).
// x staged in smem via coalesced LDG.128, double-buffered 8-step windows.
// tanh.approx for steps 0..2015; precise tanh for the last 32 steps.
// ---------------------------------------------------------------------------
__global__ __launch_bounds__(256, 1) void rnn1_kernel(
    const float* __restrict__ x,
    const float* __restrict__ wih_f, const float* __restrict__ whh_f,
    const float* __restrict__ bih_f, const float* __restrict__ bhh_f,
    const float* __restrict__ wih_b, const float* __restrict__ whh_b,
    const float* __restrict__ bih_b, const float* __restrict__ bhh_b)
{
    // [warp][buf][task*44 + idx] : 10 tasks x 40 floats (8 steps x 5), pad 44
    __shared__ float sxf[8][2][440];

    const int wIn  = threadIdx.x >> 5;
    const int lane = threadIdx.x & 31;
    const int wid  = blockIdx.x * 8 + wIn;
    if (wid >= 2 * WPD) return;

    const bool bwd = (wid >= WPD);
    const int  wg  = bwd ? wid - WPD : wid;
    const int  tri = min(lane / 3, 9);    // lanes 30,31 shadow task 9
    const int  r   = lane % 3;
    const int  rA  = (r + 1) % 3, rB = (r + 2) % 3;
    const int  laneA = 3 * tri + rA, laneB = 3 * tri + rB;

    const float* wih = bwd ? wih_b : wih_f;
    const float* whh = bwd ? whh_b : whh_f;
    const float* bih = bwd ? bih_b : bih_f;
    const float* bhh = bwd ? bhh_b : bhh_f;

    // Weight rows for units j = 3r+m, with Whh columns grouped as
    // [own triple 3r..], [lane rA's units 3rA..], [lane rB's units 3rB..]
    float Wi[3][5], WhO[3][3], WhA[3][3], WhB[3][3], Bv[3];
    #pragma unroll
    for (int m = 0; m < 3; m++) {
        const int j = 3 * r + m;
        #pragma unroll
        for (int k = 0; k < 5; k++) Wi[m][k] = wih[j * 5 + k];
        #pragma unroll
        for (int i = 0; i < 3; i++) {
            WhO[m][i] = whh[j * 9 + 3 * r  + i];
            WhA[m][i] = whh[j * 9 + 3 * rA + i];
            WhB[m][i] = whh[j * 9 + 3 * rB + i];
        }
        Bv[m] = bih[j] + bhh[j];
    }

    // ---- coalesced loader: 100 float4 chunks (task 0..9, chunk c 0..9) ----
    const char* xc = (const char*)x;
    size_t gaddr[4];
    int    soff4[4];    // float4 index into sxf row space (44 floats = 11 f4)
    #pragma unroll
    for (int k = 0; k < 4; k++) {
        int idx = min(lane + 32 * k, 99);
        int task = idx / 10, c = idx - 10 * task;
        int b = min(wg * 10 + task, BB - 1);
        gaddr[k] = (size_t)b * (TT * 20) + (size_t)c * 16;   // bytes
        soff4[k] = task * 11 + c;
    }
    float4 pf[4];

    #define PFLOAD(g) do {                                                    \
        size_t wb = (size_t)(bwd ? (TT - 8 - 8 * (g)) : (8 * (g))) * 20;      \
        _Pragma("unroll")                                                     \
        for (int k = 0; k < 4; k++)                                           \
            if (lane + 32 * k < 100)                                          \
                pf[k] = *reinterpret_cast<const float4*>(xc + gaddr[k] + wb); \
    } while (0)

    #define STSW(buf) do {                                                    \
        float4* s4 = reinterpret_cast<float4*>(&sxf[wIn][buf][0]);            \
        _Pragma("unroll")                                                     \
        for (int k = 0; k < 4; k++)                                           \
            if (lane + 32 * k < 100) s4[soff4[k]] = pf[k];                    \
    } while (0)

    // recurrent state: own h + two shuffled triples
    float h0 = 0.f, h1 = 0.f, h2 = 0.f;
    float Ha[3] = {0.f, 0.f, 0.f}, Hb[3] = {0.f, 0.f, 0.f};

    #define STEP(TANHF, buf, q) do {                                          \
        const float* xs = &sxf[wIn][buf][tri * 44 + (q) * 5];                 \
        float x0 = xs[0], x1 = xs[1], x2 = xs[2], x3 = xs[3], x4 = xs[4];     \
        float nh0, nh1, nh2;                                                  \
        _Pragma("unroll")                                                     \
        for (int m = 0; m < 3; m++) {                                         \
            float zx = Bv[m];                                                 \
            zx = fmaf(Wi[m][0], x0, zx); zx = fmaf(Wi[m][1], x1, zx);         \
            zx = fmaf(Wi[m][2], x2, zx); zx = fmaf(Wi[m][3], x3, zx);         \
            zx = fmaf(Wi[m][4], x4, zx);                                      \
            float zo = WhO[m][0] * h0;                                        \
            zo = fmaf(WhO[m][1], h1, zo); zo = fmaf(WhO[m][2], h2, zo);       \
            float za = WhA[m][0] * Ha[0];                                     \
            za = fmaf(WhA[m][1], Ha[1], za); za = fmaf(WhA[m][2], Ha[2], za); \
            float zb = WhB[m][0] * Hb[0];                                     \
            zb = fmaf(WhB[m][1], Hb[1], zb); zb = fmaf(WhB[m][2], Hb[2], zb); \
            float z = (zx + zo) + (za + zb);                                  \
            float t_ = TANHF(z);                                              \
            if (m == 0) nh0 = t_; else if (m == 1) nh1 = t_; else nh2 = t_;   \
        }                                                                     \
        h0 = nh0; h1 = nh1; h2 = nh2;                                         \
        Ha[0] = __shfl_sync(0xffffffffu, h0, laneA);                          \
        Ha[1] = __shfl_sync(0xffffffffu, h1, laneA);                          \
        Ha[2] = __shfl_sync(0xffffffffu, h2, laneA);                          \
        Hb[0] = __shfl_sync(0xffffffffu, h0, laneB);                          \
        Hb[1] = __shfl_sync(0xffffffffu, h1, laneB);                          \
        Hb[2] = __shfl_sync(0xffffffffu, h2, laneB);                          \
    } while (0)

    #define CONS(TANHF, buf) do {                                             \
        if (!bwd) {                                                           \
            STEP(TANHF, buf, 0); STEP(TANHF, buf, 1);                         \
            STEP(TANHF, buf, 2); STEP(TANHF, buf, 3);                         \
            STEP(TANHF, buf, 4); STEP(TANHF, buf, 5);                         \
            STEP(TANHF, buf, 6); STEP(TANHF, buf, 7);                         \
        } else {                                                              \
            STEP(TANHF, buf, 7); STEP(TANHF, buf, 6);                         \
            STEP(TANHF, buf, 5); STEP(TANHF, buf, 4);                         \
            STEP(TANHF, buf, 3); STEP(TANHF, buf, 2);                         \
            STEP(TANHF, buf, 1); STEP(TANHF, buf, 0);                         \
        }                                                                     \
    } while (0)

    PFLOAD(0);
    STSW(0);
    PFLOAD(1);
    __syncwarp();
    for (int g = 0; g < NWIN; g++) {
        const int buf = g & 1;
        if (g < NWIN - 4) CONS(tanha, buf);
        else              CONS(ftanh, buf);
        if (g + 1 < NWIN) {
            STSW((g + 1) & 1);
            if (g + 2 < NWIN) PFLOAD(g + 2);
            __syncwarp();
        }
    }

    const int b = wg * 10 + tri;
    if (lane < 30 && b < BB) {
        float* dst = g_y + b * 18 + (bwd ? 9 : 0) + 3 * r;
        dst[0] = h0; dst[1] = h1; dst[2] = h2;
    }
    #undef PFLOAD
    #undef STSW
    #undef STEP
    #undef CONS
}

// ---------------------------------------------------------------------------
// Stage 2: H2=32 RNN, 25 steps + linear 32->3 (unchanged from R4: 27us).
// ---------------------------------------------------------------------------
__global__ __launch_bounds__(256) void rnn2_kernel(
    const float* __restrict__ wih2, const float* __restrict__ whh2,
    const float* __restrict__ bih2, const float* __restrict__ bhh2,
    const float* __restrict__ wout, const float* __restrict__ bout,
    float* __restrict__ out)
{
    __shared__ float swh[1024], swi[576], swo[96];
    __shared__ float hs[8][OUTLEN][32];

    const int tid = threadIdx.x;
    for (int i = tid; i < 1024; i += 256) swh[i] = whh2[i];
    for (int i = tid; i < 576;  i += 256) swi[i] = wih2[i];
    if (tid < 96) swo[tid] = wout[tid];
    __syncthreads();

    const int wIn = tid >> 5;
    const int j   = tid & 31;
    const int b   = blockIdx.x * 8 + wIn;

    float Wh[32];
    {
        const float4* p = reinterpret_cast<const float4*>(&swh[j * 32]);
        #pragma unroll
        for (int c = 0; c < 8; c++) {
            float4 v = p[c];
            Wh[4*c] = v.x; Wh[4*c+1] = v.y; Wh[4*c+2] = v.z; Wh[4*c+3] = v.w;
        }
    }
    float Wi[18];
    {
        const float2* p = reinterpret_cast<const float2*>(&swi[j * 18]);
        #pragma unroll
        for (int c = 0; c < 9; c++) { float2 v = p[c]; Wi[2*c] = v.x; Wi[2*c+1] = v.y; }
    }
    const float bj = bih2[j] + bhh2[j];

    float z = bj;
    {
        const float2* yp = reinterpret_cast<const float2*>(g_y + (size_t)b * 18);
        #pragma unroll
        for (int c = 0; c < 9; c++) {
            float2 v = yp[c];
            z = fmaf(Wi[2*c], v.x, z);
            z = fmaf(Wi[2*c+1], v.y, z);
        }
    }
    float h = ftanh(z);
    hs[wIn][0][j] = h;

    for (int t = 1; t < OUTLEN; t++) {
        __syncwarp();
        const float4* hp = reinterpret_cast<const float4*>(&hs[wIn][t - 1][0]);
        float a0 = bj, a1 = 0.f, a2 = 0.f, a3 = 0.f;
        #pragma unroll
        for (int c = 0; c < 8; c += 4) {
            float4 v0 = hp[c],     v1 = hp[c + 1];
            float4 v2 = hp[c + 2], v3 = hp[c + 3];
            a0 = fmaf(Wh[4*c+0],  v0.x, a0); a0 = fmaf(Wh[4*c+1],  v0.y, a0);
            a1 = fmaf(Wh[4*c+2],  v0.z, a1); a1 = fmaf(Wh[4*c+3],  v0.w, a1);
            a2 = fmaf(Wh[4*c+4],  v1.x, a2); a2 = fmaf(Wh[4*c+5],  v1.y, a2);
            a3 = fmaf(Wh[4*c+6],  v1.z, a3); a3 = fmaf(Wh[4*c+7],  v1.w, a3);
            a0 = fmaf(Wh[4*c+8],  v2.x, a0); a0 = fmaf(Wh[4*c+9],  v2.y, a0);
            a1 = fmaf(Wh[4*c+10], v2.z, a1); a1 = fmaf(Wh[4*c+11], v2.w, a1);
            a2 = fmaf(Wh[4*c+12], v3.x, a2); a2 = fmaf(Wh[4*c+13], v3.y, a2);
            a3 = fmaf(Wh[4*c+14], v3.z, a3); a3 = fmaf(Wh[4*c+15], v3.w, a3);
        }
        h = ftanh((a0 + a1) + (a2 + a3));
        hs[wIn][t][j] = h;
    }
    __syncwarp();

    float* op = out + (size_t)b * (OUTLEN * 3);
    for (int p = j; p < OUTLEN * 3; p += 32) {
        const int t = p / 3, o = p - 3 * t;
        const float4* yr = reinterpret_cast<const float4*>(&hs[wIn][t][0]);
        const float4* wr = reinterpret_cast<const float4*>(&swo[o * 32]);
        float acc = bout[o];
        #pragma unroll
        for (int c = 0; c < 8; c++) {
            float4 yv = yr[c], wv = wr[c];
            acc = fmaf(yv.x, wv.x, acc);
            acc = fmaf(yv.y, wv.y, acc);
            acc = fmaf(yv.z, wv.z, acc);
            acc = fmaf(yv.w, wv.w, acc);
        }
        op[p] = acc;
    }
}

// ---------------------------------------------------------------------------
// Launch order is padded with no-op kernels so ncu's "-s 5 -c 1" capture
// (launch #6) lands on rnn1 (the dominant kernel) instead of rnn2:
// per call: [dummy, rnn1, rnn2, dummy] -> launch 6 = rnn1 of call 2.
// ---------------------------------------------------------------------------
extern "C" void kernel_launch(void* const* d_in, const int* in_sizes, int n_in,
                              void* d_out, int out_size)
{
    const float* x     = (const float*)d_in[0];
    const float* wih_f = (const float*)d_in[1];
    const float* whh_f = (const float*)d_in[2];
    const float* bih_f = (const float*)d_in[3];
    const float* bhh_f = (const float*)d_in[4];
    const float* wih_b = (const float*)d_in[5];
    const float* whh_b = (const float*)d_in[6];
    const float* bih_b = (const float*)d_in[7];
    const float* bhh_b = (const float*)d_in[8];
    const float* wih2  = (const float*)d_in[9];
    const float* whh2  = (const float*)d_in[10];
    const float* bih2  = (const float*)d_in[11];
    const float* bhh2  = (const float*)d_in[12];
    const float* wout  = (const float*)d_in[13];
    const float* bout  = (const float*)d_in[14];
    float* out = (float*)d_out;

    dummy_kernel<<<1, 32>>>();
    rnn1_kernel<<<103, 256>>>(x, wih_f, whh_f, bih_f, bhh_f,
                              wih_b, whh_b, bih_b, bhh_b);
    rnn2_kernel<<<512, 256>>>(wih2, whh2, bih2, bhh2, wout, bout, out);
    dummy_kernel<<<1, 32>>>();
}